// round 16
// baseline (speedup 1.0000x reference)
#include <cuda_runtime.h>
#include <cstdint>

#define NMAX 100000
#define EPSV 1e-5f
#define NITER 4

typedef unsigned long long ull;

// 16 floats per node: [0..7] = b0 + x@W0_top, [8..15] = x@W0_bot
__device__ float g_nodefeat[NMAX * 16];
__device__ int g_idx_is64;
__device__ int g_unit;            // 1 if all g==1 and all be==0
__device__ __align__(16) float g_staging[288];

// constant params (floats):
//   W1@0, W2@64, b1@128, g1@136, be1@144, b2@152, g2@160, be2@168,
//   W3@176, g0@184, be0@192, b3@200,
//   g0sw@208 (half-swapped), be0sw@216, W1sw@224 (rows k<->k^4)
__constant__ __align__(16) float c_p[288];

// ---------------- f32x2 / MUFU helpers ----------------
__device__ __forceinline__ ull pkdup(float v) {
    ull d; asm("mov.b64 %0, {%1, %1};" : "=l"(d) : "f"(v)); return d;
}
__device__ __forceinline__ void upk(ull v, float& lo, float& hi) {
    asm("mov.b64 {%0, %1}, %2;" : "=f"(lo), "=f"(hi) : "l"(v));
}
__device__ __forceinline__ ull add2(ull a, ull b) {
    ull d; asm("add.rn.f32x2 %0, %1, %2;" : "=l"(d) : "l"(a), "l"(b)); return d;
}
__device__ __forceinline__ ull mul2(ull a, ull b) {
    ull d; asm("mul.rn.f32x2 %0, %1, %2;" : "=l"(d) : "l"(a), "l"(b)); return d;
}
__device__ __forceinline__ ull fma2(ull a, ull b, ull c) {
    ull d; asm("fma.rn.f32x2 %0, %1, %2, %3;" : "=l"(d) : "l"(a), "l"(b), "l"(c)); return d;
}
__device__ __forceinline__ float tanhf_(float x) {
    float r; asm("tanh.approx.f32 %0, %1;" : "=f"(r) : "f"(x)); return r;
}
__device__ __forceinline__ float rsqf_(float x) {
    float r; asm("rsqrt.approx.f32 %0, %1;" : "=f"(r) : "f"(x)); return r;
}
__device__ __forceinline__ ull shfl64(ull v) {
    return __shfl_xor_sync(0xffffffffu, v, 1);
}
__device__ __forceinline__ ull sel_ull(bool p, ull a, ull b) { return p ? a : b; }

// ---------------- LN -> tanh blocks ----------------

__device__ __forceinline__ void ln_stats(const ull h[4], float& sc, float& m_neg) {
    ull s = add2(add2(h[0], h[1]), add2(h[2], h[3]));
    float sl, sh; upk(s, sl, sh);
    m_neg = (sl + sh) * (-0.125f);

    ull q = mul2(h[0], h[0]);
    q = fma2(h[1], h[1], q);
    q = fma2(h[2], h[2], q);
    q = fma2(h[3], h[3], q);
    float ql, qh; upk(q, ql, qh);
    float msq = (ql + qh) * 0.125f;
    float var = fmaf(-m_neg, m_neg, msq);   // msq - m^2
    sc = rsqf_(var + EPSV);
}

__device__ __forceinline__ void tanh_pair(ull r, float& y0, float& y1) {
    float u0, u1; upk(r, u0, u1);
    y0 = tanhf_(u0);
    y1 = tanhf_(u1);
}

// Unit-affine LN (g==1, be==0): apply = h*sc + m_neg*sc. No constant loads.
__device__ __forceinline__ void lnth8_unit(const ull h[4], float y[8]) {
    float sc, m_neg;
    ln_stats(h, sc, m_neg);
    ull sc2 = pkdup(sc);
    ull cm2 = pkdup(m_neg * sc);
#pragma unroll
    for (int p = 0; p < 4; p++) {
        ull r = fma2(h[p], sc2, cm2);
        tanh_pair(r, y[2 * p], y[2 * p + 1]);
    }
}

// General LN with runtime g/be pointers (constant space).
__device__ __forceinline__ void lnth8_dyn(const ull h[4], float y[8],
                                          const float* gp_, const float* bp_) {
    float sc, m_neg;
    ln_stats(h, sc, m_neg);
    ull sc2 = pkdup(sc);
    ull nm2 = pkdup(m_neg);
    const ull* gp = reinterpret_cast<const ull*>(gp_);
    const ull* bp = reinterpret_cast<const ull*>(bp_);
#pragma unroll
    for (int p = 0; p < 4; p++) {
        ull ag = mul2(sc2, gp[p]);        // s*g
        ull c  = fma2(nm2, ag, bp[p]);    // be - m*s*g
        ull r  = fma2(h[p], ag, c);       // ln(h)
        tanh_pair(r, y[2 * p], y[2 * p + 1]);
    }
}

// Dual-edge 8x8 matmul + bias; W/B via runtime constant-space pointers.
__device__ __forceinline__ void mm8s2_p(const float y0[8], const float y1[8],
                                        ull o0[4], ull o1[4],
                                        const float* W, const float* B) {
    const ull* bp = reinterpret_cast<const ull*>(B);
#pragma unroll
    for (int p = 0; p < 4; p++) {
        ull b = bp[p];
        o0[p] = b; o1[p] = b;
    }
#pragma unroll
    for (int k = 0; k < 8; k++) {
        const ull* wr = reinterpret_cast<const ull*>(W + 8 * k);
        ull w0 = wr[0], w1 = wr[1], w2 = wr[2], w3 = wr[3];
        ull h0 = pkdup(y0[k]), h1 = pkdup(y1[k]);
        o0[0] = fma2(h0, w0, o0[0]);  o1[0] = fma2(h1, w0, o1[0]);
        o0[1] = fma2(h0, w1, o0[1]);  o1[1] = fma2(h1, w1, o1[1]);
        o0[2] = fma2(h0, w2, o0[2]);  o1[2] = fma2(h1, w2, o1[2]);
        o0[3] = fma2(h0, w3, o0[3]);  o1[3] = fma2(h1, w3, o1[3]);
    }
}

// Full MLP for 2 edges. Odd lanes hold h half-swapped (local order); the
// swapped g0/be0 copies (general path) and row-swapped W1 copy absorb it.
template<bool UNIT>
__device__ __forceinline__ void mlp2(const ull h0[4], const ull h1[4], int par,
                                     float& a0, float& a1) {
    const float* w1p = c_p + (par ? 224 : 0);
    float y0[8], y1[8];
    if (UNIT) {
        lnth8_unit(h0, y0); lnth8_unit(h1, y1);
    } else {
        const float* gp = c_p + (par ? 208 : 184);
        const float* bp = c_p + (par ? 216 : 192);
        lnth8_dyn(h0, y0, gp, bp); lnth8_dyn(h1, y1, gp, bp);
    }
    ull p0[4], p1[4];
    mm8s2_p(y0, y1, p0, p1, w1p, c_p + 128);          // W1(sw), b1
    if (UNIT) {
        lnth8_unit(p0, y0); lnth8_unit(p1, y1);
    } else {
        lnth8_dyn(p0, y0, c_p + 136, c_p + 144);
        lnth8_dyn(p1, y1, c_p + 136, c_p + 144);
    }
    mm8s2_p(y0, y1, p0, p1, c_p + 64, c_p + 152);     // W2, b2
    if (UNIT) {
        lnth8_unit(p0, y0); lnth8_unit(p1, y1);
    } else {
        lnth8_dyn(p0, y0, c_p + 160, c_p + 168);
        lnth8_dyn(p1, y1, c_p + 160, c_p + 168);
    }
    a0 = c_p[200]; a1 = c_p[200];
#pragma unroll
    for (int i = 0; i < 8; i++) {
        float w = c_p[176 + i];
        a0 = fmaf(y0[i], w, a0);
        a1 = fmaf(y1[i], w, a1);
    }
}

// Load the 4 pair-edge index pairs for quad base q4 (clamped at tail).
__device__ __forceinline__ void load_idx4(const void* __restrict__ ei_raw, bool is64,
                                          int q4, int E, int Em1,
                                          int s4[4], int d4[4]) {
    if (is64) {
        const long long* ei = (const long long*)ei_raw;
        if ((q4 + 3 < E) && ((E & 1) == 0)) {
            longlong2 a  = *reinterpret_cast<const longlong2*>(ei + q4);
            longlong2 b  = *reinterpret_cast<const longlong2*>(ei + q4 + 2);
            longlong2 c  = *reinterpret_cast<const longlong2*>(ei + E + q4);
            longlong2 dd = *reinterpret_cast<const longlong2*>(ei + E + q4 + 2);
            s4[0] = (int)a.x; s4[1] = (int)a.y; s4[2] = (int)b.x; s4[3] = (int)b.y;
            d4[0] = (int)c.x; d4[1] = (int)c.y; d4[2] = (int)dd.x; d4[3] = (int)dd.y;
        } else {
#pragma unroll
            for (int i = 0; i < 4; i++) {
                int ce = min(q4 + i, Em1);
                s4[i] = (int)ei[ce];
                d4[i] = (int)ei[E + ce];
            }
        }
    } else {
        const int* ei = (const int*)ei_raw;
        if ((q4 + 3 < E) && ((E & 3) == 0)) {
            int4 sv = *reinterpret_cast<const int4*>(ei + q4);
            int4 dv = *reinterpret_cast<const int4*>(ei + E + q4);
            s4[0] = sv.x; s4[1] = sv.y; s4[2] = sv.z; s4[3] = sv.w;
            d4[0] = dv.x; d4[1] = dv.y; d4[2] = dv.z; d4[3] = dv.w;
        } else {
#pragma unroll
            for (int i = 0; i < 4; i++) {
                int ce = min(q4 + i, Em1);
                s4[i] = ei[ce];
                d4[i] = ei[E + ce];
            }
        }
    }
}

// ---------------- kernel 1: node precompute + dtype detect + param staging ----
__global__ void node_prep(const float* __restrict__ x, const float* __restrict__ W0,
                          const float* __restrict__ b0, const void* __restrict__ ei,
                          const float* __restrict__ W1, const float* __restrict__ b1,
                          const float* __restrict__ g1, const float* __restrict__ be1,
                          const float* __restrict__ W2, const float* __restrict__ b2,
                          const float* __restrict__ g2, const float* __restrict__ be2,
                          const float* __restrict__ W3, const float* __restrict__ b3,
                          const float* __restrict__ g0, const float* __restrict__ be0,
                          int N) {
    __shared__ int s_flag;
    if (blockIdx.x == 0) {
        if (threadIdx.x == 0) s_flag = 1;
        __syncthreads();
        long long v = ((const long long*)ei)[threadIdx.x];
        if (v < 0 || v >= (long long)N) s_flag = 0;   // benign race
        __syncthreads();
        if (threadIdx.x == 0) g_idx_is64 = s_flag;
    } else if (blockIdx.x == 1) {
        if (threadIdx.x == 0) s_flag = 1;
        __syncthreads();
        int t = threadIdx.x;
        int bad = 0;
        if (t < 64) {
            g_staging[t] = W1[t];
        } else if (t < 128) {
            g_staging[t] = W2[t - 64];
        } else if (t < 208) {
            int i = t - 128, grp = i >> 3, j = i & 7;
            float v;
            switch (grp) {
                case 0: v = b1[j]; break;
                case 1: v = g1[j]; if (v != 1.0f) bad = 1; break;
                case 2: v = be1[j]; if (v != 0.0f) bad = 1; break;
                case 3: v = b2[j]; break;
                case 4: v = g2[j]; if (v != 1.0f) bad = 1; break;
                case 5: v = be2[j]; if (v != 0.0f) bad = 1; break;
                case 6: v = W3[j]; break;
                case 7: v = g0[j]; if (v != 1.0f) bad = 1; break;
                case 8: v = be0[j]; if (v != 0.0f) bad = 1; break;
                default: v = (j == 0) ? b3[0] : 0.0f; break;
            }
            g_staging[128 + i] = v;
        } else if (t < 216) {              // g0 half-swapped
            int j = t - 208;
            g_staging[t] = g0[j ^ 4];
        } else if (t < 224) {              // be0 half-swapped
            int j = t - 216;
            g_staging[t] = be0[j ^ 4];
        } else {                           // W1 rows k<->k^4, rows 0..3 part
            int i = t - 224;
            g_staging[t] = W1[(((i >> 3) ^ 4) << 3) + (i & 7)];
        }
        if (bad) s_flag = 0;               // benign race
        __syncthreads();
        if (threadIdx.x == 0) g_unit = s_flag;
    } else if (blockIdx.x == 2 && threadIdx.x < 32) {
        int t = 256 + threadIdx.x;         // W1sw rows 4..7 part
        int i = t - 224;
        g_staging[t] = W1[(((i >> 3) ^ 4) << 3) + (i & 7)];
    }

    int n = blockIdx.x * blockDim.x + threadIdx.x;
    if (n >= N) return;
    float x0 = x[n * 3 + 0], x1 = x[n * 3 + 1], x2 = x[n * 3 + 2];
    float t[16];
#pragma unroll
    for (int j = 0; j < 8; j++) {
        t[j]     = b0[j] + x0 * W0[j] + x1 * W0[8 + j] + x2 * W0[16 + j];
        t[8 + j] =         x0 * W0[24 + j] + x1 * W0[32 + j] + x2 * W0[40 + j];
    }
    float4* dst = reinterpret_cast<float4*>(g_nodefeat + (size_t)n * 16);
#pragma unroll
    for (int q = 0; q < 4; q++)
        dst[q] = make_float4(t[4 * q], t[4 * q + 1], t[4 * q + 2], t[4 * q + 3]);
}

// ---------------- kernel 2: per-edge MLP, pipelined grid-strided loop ----
// Lane pair handles NITER edge-quads spaced pairs_total apart. Indices for
// iteration it+1 are loaded at the top of iteration it -> their DRAM/L2
// latency hides under the current iteration's MLP. Gather stays pair-coop
// (one 128B line per pair per instruction).
__global__ __launch_bounds__(128, 10)
void edge_kernel(const void* __restrict__ ei_raw, float* __restrict__ out,
                 int E, int pairs_total) {
    int t = blockIdx.x * blockDim.x + threadIdx.x;
    int par = threadIdx.x & 1;
    int pair = t >> 1;
    int Em1 = E - 1;
    bool is64 = (g_idx_is64 != 0);
    bool unit = (g_unit != 0);
    bool p = (par != 0);

    const ulonglong2* nf = reinterpret_cast<const ulonglong2*>(g_nodefeat);

    int s4[4], d4[4], s4n[4], d4n[4];
    load_idx4(ei_raw, is64, pair * 4, E, Em1, s4, d4);

#pragma unroll 1
    for (int it = 0; it < NITER; it++) {
        int q4 = (pair + it * pairs_total) * 4;
        if (it + 1 < NITER) {
            load_idx4(ei_raw, is64, (pair + (it + 1) * pairs_total) * 4, E, Em1,
                      s4n, d4n);
        }

        // pair-uniform gather: my-par 16B slice of each pair-edge's h
        ull hXa[4], hXb[4];
#pragma unroll
        for (int i = 0; i < 4; i++) {
            ulonglong2 Ls = nf[4 * s4[i] + par];        // s-top slice
            ulonglong2 Ld = nf[4 * d4[i] + 2 + par];    // d-bot slice
            hXa[i] = add2(Ls.x, Ld.x);
            hXb[i] = add2(Ls.y, Ld.y);
        }

        // exchange: send my halves of partner's edges, keep mine
        ull sendAa = sel_ull(p, hXa[0], hXa[2]), sendAb = sel_ull(p, hXb[0], hXb[2]);
        ull sendBa = sel_ull(p, hXa[1], hXa[3]), sendBb = sel_ull(p, hXb[1], hXb[3]);
        ull keepAa = sel_ull(p, hXa[2], hXa[0]), keepAb = sel_ull(p, hXb[2], hXb[0]);
        ull keepBa = sel_ull(p, hXa[3], hXa[1]), keepBb = sel_ull(p, hXb[3], hXb[1]);
        ull rAa = shfl64(sendAa), rAb = shfl64(sendAb);
        ull rBa = shfl64(sendBa), rBb = shfl64(sendBb);

        // local-order h: [my-par half, partner-par half]
        ull h0[4] = {keepAa, keepAb, rAa, rAb};
        ull h1[4] = {keepBa, keepBb, rBa, rBb};

        float a0, a1;
        if (unit) mlp2<true>(h0, h1, par, a0, a1);
        else      mlp2<false>(h0, h1, par, a0, a1);

        int e0 = q4 + 2 * par;
        if (e0 + 1 < E && q4 + 3 < E) {
            *reinterpret_cast<float2*>(out + e0) = make_float2(a0, a1);
        } else {
            if (e0 < E)     out[e0] = a0;
            if (e0 + 1 < E) out[e0 + 1] = a1;
        }

        if (it + 1 < NITER) {
#pragma unroll
            for (int i = 0; i < 4; i++) { s4[i] = s4n[i]; d4[i] = d4n[i]; }
        }
    }
}

// ---------------- launch ----------------
extern "C" void kernel_launch(void* const* d_in, const int* in_sizes, int n_in,
                              void* d_out, int out_size) {
    const float* x   = (const float*)d_in[0];
    const void*  ei  = (const void*)d_in[1];
    const float* W0  = (const float*)d_in[2];
    const float* b0  = (const float*)d_in[3];
    const float* g0  = (const float*)d_in[4];
    const float* be0 = (const float*)d_in[5];
    const float* W1  = (const float*)d_in[6];
    const float* b1  = (const float*)d_in[7];
    const float* g1  = (const float*)d_in[8];
    const float* be1 = (const float*)d_in[9];
    const float* W2  = (const float*)d_in[10];
    const float* b2  = (const float*)d_in[11];
    const float* g2  = (const float*)d_in[12];
    const float* be2 = (const float*)d_in[13];
    const float* W3  = (const float*)d_in[14];
    const float* b3  = (const float*)d_in[15];
    float* out = (float*)d_out;

    int N = in_sizes[0] / 3;
    if (N > NMAX) N = NMAX;
    int E = in_sizes[1] / 2;

    int nblocks = (N + 255) / 256;
    if (nblocks < 3) nblocks = 3;
    node_prep<<<nblocks, 256>>>(x, W0, b0, ei, W1, b1, g1, be1,
                                W2, b2, g2, be2, W3, b3, g0, be0, N);

    void* staging_ptr = nullptr;
    cudaGetSymbolAddress(&staging_ptr, g_staging);
    cudaMemcpyToSymbolAsync(c_p, staging_ptr, 288 * sizeof(float), 0,
                            cudaMemcpyDeviceToDevice);

    int quads = (E + 3) / 4;
    int pairs_total = (quads + NITER - 1) / NITER;
    int threads = pairs_total * 2;
    edge_kernel<<<(threads + 127) / 128, 128>>>(ei, out, E, pairs_total);
}